// round 5
// baseline (speedup 1.0000x reference)
#include <cuda_runtime.h>
#include <cuda_bf16.h>
#include <math.h>
#include <stdint.h>

// Problem constants
#define B_    256
#define IC    1152
#define NU_   10
#define US    16
#define IU    8
#define NUU   160       // NU_*US
#define KTOT  9216      // IU*IC
#define KSPLIT 72       // hmma1 k-splits (128 k per CTA)
#define SA    72        // smem row stride (bf16): 144B -> bank stride 4 mod 32

// ---------------- device scratch ----------------
__device__ __align__(128) __nv_bfloat16 g_xh [B_ * KTOT];
__device__ __align__(128) __nv_bfloat16 g_xl [B_ * KTOT];
__device__ __align__(128) __nv_bfloat16 g_xth[KTOT * B_];
__device__ __align__(128) __nv_bfloat16 g_xtl[KTOT * B_];
__device__ __align__(128) float g_Wnk[NUU * KTOT];
__device__ __align__(128) float g_Wkn[KTOT * NUU];
__device__ __align__(128) __nv_bfloat16 g_SWth[NUU * KTOT];
__device__ __align__(128) __nv_bfloat16 g_SWtl[NUU * KTOT];
__device__ __align__(128) __nv_bfloat16 g_Vth[NUU * B_];
__device__ __align__(128) __nv_bfloat16 g_Vtl[NUU * B_];
__device__ __align__(128) float g_Spart[KSPLIT * B_ * NUU];
__device__ __align__(128) float g_bp[16 * IC * NU_];     // [i*2+bsplit][j][n]
__device__ float g_logits[IC * NU_];
__device__ float g_ct[NU_ * IC];

// ---------------- asm helpers ----------------
__device__ __forceinline__ uint32_t smem_to_u32(const void* p) {
    uint32_t a;
    asm("{ .reg .u64 t; cvta.to.shared.u64 t, %1; cvt.u32.u64 %0, t; }" : "=r"(a) : "l"(p));
    return a;
}
__device__ __forceinline__ void cpasync(uint32_t d, const void* g) {
    asm volatile("cp.async.cg.shared.global [%0], [%1], 16;" :: "r"(d), "l"(g));
}
#define CP_COMMIT() asm volatile("cp.async.commit_group;" ::: "memory")
#define CP_WAIT(n)  asm volatile("cp.async.wait_group %0;" :: "n"(n) : "memory")

__device__ __forceinline__ void ldsm_x4(uint32_t* r, uint32_t addr) {
    asm volatile("ldmatrix.sync.aligned.m8n8.x4.shared.b16 {%0,%1,%2,%3}, [%4];"
                 : "=r"(r[0]), "=r"(r[1]), "=r"(r[2]), "=r"(r[3]) : "r"(addr));
}
__device__ __forceinline__ void mma4(float* c, const uint32_t* a, uint32_t b0, uint32_t b1) {
    asm volatile("mma.sync.aligned.m16n8k16.row.col.f32.bf16.bf16.f32 "
        "{%0,%1,%2,%3}, {%4,%5,%6,%7}, {%8,%9}, {%0,%1,%2,%3};"
        : "+f"(c[0]), "+f"(c[1]), "+f"(c[2]), "+f"(c[3])
        : "r"(a[0]), "r"(a[1]), "r"(a[2]), "r"(a[3]), "r"(b0), "r"(b1));
}

// ---------------- shared GEMM pieces (M=128, N=160, chunk=64k) ----------------
#define BUF (576 * SA * 2)            // 82944 B per buffer
#define GSMEM (2 * BUF)               // 165888 B

// load one 64-col chunk of A(128 rows) hi/lo + B(160 rows) hi/lo
__device__ __forceinline__ void g_load128(uint32_t sb,
        const __nv_bfloat16* __restrict__ Ah, const __nv_bfloat16* __restrict__ Al,
        const __nv_bfloat16* __restrict__ Bh, const __nv_bfloat16* __restrict__ Bl,
        int strideA, int strideB, int tid) {
#pragma unroll
    for (int t = 0; t < 4; t++) {
        int idx = tid + t * 256;
        int r = idx >> 3, q = idx & 7;
        uint32_t d = sb + (uint32_t)(r * SA + q * 8) * 2;
        size_t g = (size_t)r * strideA + q * 8;
        cpasync(d, Ah + g);
        cpasync(d + 128 * SA * 2, Al + g);
    }
#pragma unroll
    for (int t = 0; t < 5; t++) {
        int idx = tid + t * 256;
        int r = idx >> 3, q = idx & 7;
        uint32_t d = sb + 256 * SA * 2 + (uint32_t)(r * SA + q * 8) * 2;
        size_t g = (size_t)r * strideB + q * 8;
        cpasync(d, Bh + g);
        cpasync(d + 160 * SA * 2, Bl + g);
    }
}

// compute one 64-col chunk; warp tile 32x80, 3-pass bf16 split
__device__ __forceinline__ void compute128(uint32_t base,
        int aR0, int aR1, int bR0, float acc[2][10][4]) {
    const uint32_t aH = base, aL = base + 128 * SA * 2;
    const uint32_t bH = base + 256 * SA * 2, bL = base + 416 * SA * 2;
#pragma unroll
    for (int kk = 0; kk < 4; kk++) {
        const int kb2 = kk * 32;
        uint32_t ah[2][4], al[2][4];
        ldsm_x4(ah[0], aH + aR0 + kb2);
        ldsm_x4(al[0], aL + aR0 + kb2);
        ldsm_x4(ah[1], aH + aR1 + kb2);
        ldsm_x4(al[1], aL + aR1 + kb2);
#pragma unroll
        for (int fp = 0; fp < 5; fp++) {
            const int boff = bR0 + fp * (16 * SA * 2) + kb2;
            uint32_t bh[4], bl[4];
            ldsm_x4(bh, bH + boff);
            ldsm_x4(bl, bL + boff);
#pragma unroll
            for (int mf = 0; mf < 2; mf++) {
                mma4(acc[mf][2 * fp],     ah[mf], bh[0], bh[2]);
                mma4(acc[mf][2 * fp],     ah[mf], bl[0], bl[2]);
                mma4(acc[mf][2 * fp],     al[mf], bh[0], bh[2]);
                mma4(acc[mf][2 * fp + 1], ah[mf], bh[1], bh[3]);
                mma4(acc[mf][2 * fp + 1], ah[mf], bl[1], bl[3]);
                mma4(acc[mf][2 * fp + 1], al[mf], bh[1], bh[3]);
            }
        }
    }
}

// ---------------------------------------------------------------------------
// k_prex: split x -> bf16 hi/lo, row-major and transposed. grid (144,4)x256
// ---------------------------------------------------------------------------
__global__ void k_prex(const float* __restrict__ x) {
    __shared__ unsigned sh[64][65];
    const int k0 = blockIdx.x * 64, b0 = blockIdx.y * 64;
    const int tid = threadIdx.x;
#pragma unroll
    for (int i = 0; i < 16; i++) {
        int idx = tid + i * 256;
        int r = idx >> 6, c = idx & 63;
        size_t g = (size_t)(b0 + r) * KTOT + k0 + c;
        float v = x[g];
        __nv_bfloat16 h = __float2bfloat16_rn(v);
        __nv_bfloat16 l = __float2bfloat16_rn(v - __bfloat162float(h));
        g_xh[g] = h; g_xl[g] = l;
        sh[r][c] = ((unsigned)__bfloat16_as_ushort(l) << 16) | (unsigned)__bfloat16_as_ushort(h);
    }
    __syncthreads();
#pragma unroll
    for (int i = 0; i < 16; i++) {
        int idx = tid + i * 256;
        int rr = idx >> 6, cc = idx & 63;
        unsigned p = sh[cc][rr];
        size_t g = (size_t)(k0 + rr) * B_ + b0 + cc;
        g_xth[g] = __ushort_as_bfloat16((unsigned short)(p & 0xFFFF));
        g_xtl[g] = __ushort_as_bfloat16((unsigned short)(p >> 16));
    }
}

// ---------------------------------------------------------------------------
// k_pre_w: W[j,n,u,i] -> Wnk[nu][k], Wkn[k][nu], SW0 = split(W/IC);
// init logits. grid 144x256
// ---------------------------------------------------------------------------
__global__ void k_pre_w(const float* __restrict__ W) {
    __shared__ float sm[8 * 1281];
    const int j0 = blockIdx.x * 8;
    const int tid = threadIdx.x;
#pragma unroll
    for (int i = 0; i < 40; i++) {
        int idx = tid + i * 256;
        int jl = idx / 1280, rem = idx - jl * 1280;
        sm[jl * 1281 + rem] = W[(size_t)(j0 + jl) * 1280 + rem];
    }
    __syncthreads();
#pragma unroll
    for (int t = 0; t < 40; t++) {
        int idx = tid + t * 256;                 // = nu*64 + ii*8 + jl
        int jl = idx & 7, ii = (idx >> 3) & 7, nu = idx >> 6;
        float v = sm[jl * 1281 + nu * 8 + ii];
        size_t gi = (size_t)nu * KTOT + ii * IC + j0 + jl;
        g_Wnk[gi] = v;
        float vs = v * (1.0f / (float)IC);       // iter-0 c is uniform
        __nv_bfloat16 h = __float2bfloat16_rn(vs);
        g_SWth[gi] = h;
        g_SWtl[gi] = __float2bfloat16_rn(vs - __bfloat162float(h));
    }
#pragma unroll
    for (int t = 0; t < 40; t++) {
        int idx = tid + t * 256;                 // = (ii*8 + jl)*160 + nu
        int nu = idx % 160, rest = idx / 160;
        int jl = rest & 7, ii = rest >> 3;
        g_Wkn[(size_t)(ii * IC + j0 + jl) * NUU + nu] = sm[jl * 1281 + nu * 8 + ii];
    }
    int gidx = blockIdx.x * 256 + tid;
    if (gidx < IC * NU_) g_logits[gidx] = 0.0f;
}

// ---------------------------------------------------------------------------
// k_scale: SWt_{hi,lo}[nu][k] = split(Wnk[nu][k] * c[n][j]). grid 160x256
// ---------------------------------------------------------------------------
__global__ void k_scale() {
    __shared__ float cs[IC];
    const int nu = blockIdx.x;
    const int n = nu >> 4;
    const int tid = threadIdx.x;
    for (int t = tid; t < IC; t += 256) cs[t] = g_ct[n * IC + t];
    __syncthreads();
#pragma unroll
    for (int i = 0; i < 9; i++) {
        int e4 = tid + i * 256;
        int k = e4 * 4;
        int j = k % IC;
        float4 w = *reinterpret_cast<const float4*>(g_Wnk + (size_t)nu * KTOT + k);
        float v0 = w.x * cs[j], v1 = w.y * cs[j + 1], v2 = w.z * cs[j + 2], v3 = w.w * cs[j + 3];
        __nv_bfloat16 h0 = __float2bfloat16_rn(v0), h1 = __float2bfloat16_rn(v1);
        __nv_bfloat16 h2 = __float2bfloat16_rn(v2), h3 = __float2bfloat16_rn(v3);
        __nv_bfloat16 l0 = __float2bfloat16_rn(v0 - __bfloat162float(h0));
        __nv_bfloat16 l1 = __float2bfloat16_rn(v1 - __bfloat162float(h1));
        __nv_bfloat16 l2 = __float2bfloat16_rn(v2 - __bfloat162float(h2));
        __nv_bfloat16 l3 = __float2bfloat16_rn(v3 - __bfloat162float(h3));
        uint2 ph, pl;
        ph.x = ((unsigned)__bfloat16_as_ushort(h1) << 16) | __bfloat16_as_ushort(h0);
        ph.y = ((unsigned)__bfloat16_as_ushort(h3) << 16) | __bfloat16_as_ushort(h2);
        pl.x = ((unsigned)__bfloat16_as_ushort(l1) << 16) | __bfloat16_as_ushort(l0);
        pl.y = ((unsigned)__bfloat16_as_ushort(l3) << 16) | __bfloat16_as_ushort(l2);
        *reinterpret_cast<uint2*>(g_SWth + (size_t)nu * KTOT + k) = ph;
        *reinterpret_cast<uint2*>(g_SWtl + (size_t)nu * KTOT + k) = pl;
    }
}

// ---------------------------------------------------------------------------
// GEMM1: Spart[ks][b-tile 128][nu] = X * (c.W)^T over 128-k. grid 144x256.
// ---------------------------------------------------------------------------
__global__ void __launch_bounds__(256) k_hmma1() {
    extern __shared__ char sm[];
    const int mt = blockIdx.x & 1, ks = blockIdx.x >> 1;
    const int m0 = mt * 128, kbase = ks * 128;
    const int tid = threadIdx.x, warp = tid >> 5, lane = tid & 31;
    const int wm = warp & 3, wn = warp >> 2;
    const int lg = lane >> 2, lt = lane & 3;
    const uint32_t sb = smem_to_u32(sm);

    const int aR0 = ((wm * 32 + (lane & 15)) * SA + (lane >> 4) * 8) * 2;
    const int aR1 = aR0 + 16 * SA * 2;
    const int bR0 = ((wn * 80 + (lane & 15)) * SA + (lane >> 4) * 8) * 2;

    float acc[2][10][4];
#pragma unroll
    for (int mf = 0; mf < 2; mf++)
#pragma unroll
        for (int f = 0; f < 10; f++)
#pragma unroll
            for (int q = 0; q < 4; q++) acc[mf][f][q] = 0.0f;

    const __nv_bfloat16* Ah = g_xh + (size_t)m0 * KTOT + kbase;
    const __nv_bfloat16* Al = g_xl + (size_t)m0 * KTOT + kbase;
    const __nv_bfloat16* Bh = g_SWth + kbase;
    const __nv_bfloat16* Bl = g_SWtl + kbase;

    g_load128(sb,       Ah,      Al,      Bh,      Bl,      KTOT, KTOT, tid); CP_COMMIT();
    g_load128(sb + BUF, Ah + 64, Al + 64, Bh + 64, Bl + 64, KTOT, KTOT, tid); CP_COMMIT();

    CP_WAIT(1); __syncthreads();
    compute128(sb, aR0, aR1, bR0, acc);
    CP_WAIT(0); __syncthreads();
    compute128(sb + BUF, aR0, aR1, bR0, acc);

    float* base = g_Spart + (size_t)ks * (B_ * NUU);
#pragma unroll
    for (int mf = 0; mf < 2; mf++) {
        const int r0 = m0 + wm * 32 + mf * 16 + lg;
#pragma unroll
        for (int f = 0; f < 10; f++) {
            const int nu = wn * 80 + f * 8 + lt * 2;
            *reinterpret_cast<float2*>(base + (size_t)r0 * NUU + nu)       = make_float2(acc[mf][f][0], acc[mf][f][1]);
            *reinterpret_cast<float2*>(base + (size_t)(r0 + 8) * NUU + nu) = make_float2(acc[mf][f][2], acc[mf][f][3]);
        }
    }
}

// ---------------------------------------------------------------------------
// GEMM2 + fused b-update partials:
//   G[k, nu] = sum_{b in half} Xt[k][b] Vt[nu][b]; then per (j, n):
//   bp[i*2+bsplit][j][n] = sum_u W[k][nu] * G[k][nu].
// grid 144 (= kt 0..71 x bsplit), 256 threads.
// ---------------------------------------------------------------------------
__global__ void __launch_bounds__(256) k_hmma2() {
    extern __shared__ char sm[];
    const int bsplit = blockIdx.x & 1, kt = blockIdx.x >> 1;
    const int k0 = kt * 128, col0 = bsplit * 128;
    const int tid = threadIdx.x, warp = tid >> 5, lane = tid & 31;
    const int wm = warp & 3, wn = warp >> 2;
    const int lg = lane >> 2, lt = lane & 3;
    const uint32_t sb = smem_to_u32(sm);

    const int aR0 = ((wm * 32 + (lane & 15)) * SA + (lane >> 4) * 8) * 2;
    const int aR1 = aR0 + 16 * SA * 2;
    const int bR0 = ((wn * 80 + (lane & 15)) * SA + (lane >> 4) * 8) * 2;

    float acc[2][10][4];
#pragma unroll
    for (int mf = 0; mf < 2; mf++)
#pragma unroll
        for (int f = 0; f < 10; f++)
#pragma unroll
            for (int q = 0; q < 4; q++) acc[mf][f][q] = 0.0f;

    const __nv_bfloat16* Ah = g_xth + (size_t)k0 * B_ + col0;
    const __nv_bfloat16* Al = g_xtl + (size_t)k0 * B_ + col0;
    const __nv_bfloat16* Bh = g_Vth + col0;
    const __nv_bfloat16* Bl = g_Vtl + col0;

    g_load128(sb,       Ah,      Al,      Bh,      Bl,      B_, B_, tid); CP_COMMIT();
    g_load128(sb + BUF, Ah + 64, Al + 64, Bh + 64, Bl + 64, B_, B_, tid); CP_COMMIT();

    CP_WAIT(1); __syncthreads();
    compute128(sb, aR0, aR1, bR0, acc);
    CP_WAIT(0); __syncthreads();
    compute128(sb + BUF, aR0, aR1, bR0, acc);

    // fused epilogue: contract with Wkn, quad-reduce over lt, emit bp partials
    const int i_idx = k0 / IC;                 // 128-tiles align within i (1152 = 9*128)
    const int j0 = k0 % IC;
    float* bp = g_bp + ((size_t)(i_idx * 2 + bsplit) * IC + j0) * NU_;
#pragma unroll
    for (int mf = 0; mf < 2; mf++) {
        const int rbase = wm * 32 + mf * 16 + lg;
#pragma unroll
        for (int rh = 0; rh < 2; rh++) {
            const int row = rbase + rh * 8;
            const float* wrow = g_Wkn + (size_t)(k0 + row) * NUU;
#pragma unroll
            for (int q = 0; q < 5; q++) {
                const int f0 = 2 * q;
                const int nu0 = wn * 80 + f0 * 8 + lt * 2;
                float2 w0 = *reinterpret_cast<const float2*>(wrow + nu0);
                float2 w1 = *reinterpret_cast<const float2*>(wrow + nu0 + 8);
                float s = acc[mf][f0][rh * 2] * w0.x + acc[mf][f0][rh * 2 + 1] * w0.y
                        + acc[mf][f0 + 1][rh * 2] * w1.x + acc[mf][f0 + 1][rh * 2 + 1] * w1.y;
                s += __shfl_xor_sync(0xffffffffu, s, 1);
                s += __shfl_xor_sync(0xffffffffu, s, 2);
                if (lt == 0) bp[(size_t)row * NU_ + wn * 5 + q] = s;
            }
        }
    }
}

// ---------------------------------------------------------------------------
// k_squash: reduce split-K, squash; emit bf16-split V^T or final output
// ---------------------------------------------------------------------------
__global__ void k_squash(float* __restrict__ out, int final_iter) {
    const int b = blockIdx.x;
    const int t = threadIdx.x;      // t = n*16 + u
    float s = 0.0f;
#pragma unroll 8
    for (int ks = 0; ks < KSPLIT; ks++)
        s += g_Spart[(size_t)ks * (B_ * NUU) + b * NUU + t];

    __shared__ float sq[NUU];
    __shared__ float mag[US];
    sq[t] = s * s;
    __syncthreads();
    if (t < US) {
        float m = 0.0f;
#pragma unroll
        for (int n = 0; n < NU_; n++) m += sq[n * US + t];
        mag[t] = m;
    }
    __syncthreads();
    float m = mag[t & 15];
    float v = s * (m / ((1.0f + m) * sqrtf(m)));
    if (final_iter) {
        out[b * NUU + t] = v;
    } else {
        __nv_bfloat16 h = __float2bfloat16_rn(v);
        __nv_bfloat16 l = __float2bfloat16_rn(v - __bfloat162float(h));
        g_Vth[t * B_ + b] = h;
        g_Vtl[t * B_ + b] = l;
    }
}

// ---------------------------------------------------------------------------
// k_softmax: logits[j,n] += (1/B)*sum_{p<16} bp[p][j][n]; softmax over j -> ct
// 1 block, 10 warps (warp = n), lane covers 36 j's.
// ---------------------------------------------------------------------------
__global__ void k_softmax() {
    const int t = threadIdx.x;
    const int n = t >> 5;
    const int lane = t & 31;
    float vals[36];
    float mx = -1e30f;
#pragma unroll
    for (int it = 0; it < 36; it++) {
        int j = lane + it * 32;
        float d = 0.0f;
#pragma unroll
        for (int p = 0; p < 16; p++)
            d += g_bp[((size_t)p * IC + j) * NU_ + n];
        float lv = g_logits[j * NU_ + n] + d * (1.0f / (float)B_);
        g_logits[j * NU_ + n] = lv;
        vals[it] = lv;
        mx = fmaxf(mx, lv);
    }
#pragma unroll
    for (int off = 16; off; off >>= 1)
        mx = fmaxf(mx, __shfl_xor_sync(0xffffffffu, mx, off));
    float sum = 0.0f;
#pragma unroll
    for (int it = 0; it < 36; it++) { vals[it] = expf(vals[it] - mx); sum += vals[it]; }
#pragma unroll
    for (int off = 16; off; off >>= 1)
        sum += __shfl_xor_sync(0xffffffffu, sum, off);
    float inv = 1.0f / sum;
#pragma unroll
    for (int it = 0; it < 36; it++) {
        int j = lane + it * 32;
        g_ct[n * IC + j] = vals[it] * inv;
    }
}

// ---------------------------------------------------------------------------
extern "C" void kernel_launch(void* const* d_in, const int* in_sizes, int n_in,
                              void* d_out, int out_size) {
    const float* x = (const float*)d_in[0];   // [256, 8, 1152]
    const float* W = (const float*)d_in[1];   // [1152, 10, 16, 8]
    float* out = (float*)d_out;

    cudaFuncSetAttribute(k_hmma1, cudaFuncAttributeMaxDynamicSharedMemorySize, GSMEM);
    cudaFuncSetAttribute(k_hmma2, cudaFuncAttributeMaxDynamicSharedMemorySize, GSMEM);

    k_prex<<<dim3(KTOT / 64, B_ / 64), 256>>>(x);
    k_pre_w<<<IC / 8, 256>>>(W);              // also emits iter-0 scaled W split

    // iter 0
    k_hmma1<<<2 * KSPLIT, 256, GSMEM>>>();
    k_squash<<<B_, NUU>>>(nullptr, 0);
    k_hmma2<<<144, 256, GSMEM>>>();
    k_softmax<<<1, 320>>>();
    // iter 1
    k_scale<<<NUU, 256>>>();
    k_hmma1<<<2 * KSPLIT, 256, GSMEM>>>();
    k_squash<<<B_, NUU>>>(nullptr, 0);
    k_hmma2<<<144, 256, GSMEM>>>();
    k_softmax<<<1, 320>>>();
    // iter 2 (final)
    k_scale<<<NUU, 256>>>();
    k_hmma1<<<2 * KSPLIT, 256, GSMEM>>>();
    k_squash<<<B_, NUU>>>(out, 1);
}

// round 6
// speedup vs baseline: 1.7634x; 1.7634x over previous
#include <cuda_runtime.h>
#include <cuda_bf16.h>
#include <math.h>
#include <stdint.h>

// Problem constants
#define B_    256
#define IC    1152
#define NU_   10
#define US    16
#define IU    8
#define NUU   160       // NU_*US
#define KTOT  9216      // IU*IC
#define KSPLIT 36
#define SA    72        // smem row stride (bf16): 144B -> bank stride 4 mod 32

// ---------------- device scratch ----------------
__device__ __align__(128) __nv_bfloat16 g_xh [B_ * KTOT];
__device__ __align__(128) __nv_bfloat16 g_xl [B_ * KTOT];
__device__ __align__(128) __nv_bfloat16 g_xth[KTOT * B_];
__device__ __align__(128) __nv_bfloat16 g_xtl[KTOT * B_];
__device__ __align__(128) float g_Wnk[NUU * KTOT];
__device__ __align__(128) float g_Wkn[KTOT * NUU];
__device__ __align__(128) __nv_bfloat16 g_SWth[NUU * KTOT];
__device__ __align__(128) __nv_bfloat16 g_SWtl[NUU * KTOT];
__device__ __align__(128) __nv_bfloat16 g_Vth[NUU * B_];
__device__ __align__(128) __nv_bfloat16 g_Vtl[NUU * B_];
__device__ __align__(128) float g_Spart[KSPLIT * B_ * NUU];
__device__ __align__(128) float g_bp[16 * IC * NU_];     // [i*2+bsplit][j][n]
__device__ float g_logits[IC * NU_];
__device__ float g_ct[NU_ * IC];

// ---------------- asm helpers ----------------
__device__ __forceinline__ uint32_t smem_to_u32(const void* p) {
    uint32_t a;
    asm("{ .reg .u64 t; cvta.to.shared.u64 t, %1; cvt.u32.u64 %0, t; }" : "=r"(a) : "l"(p));
    return a;
}
__device__ __forceinline__ void cpasync(uint32_t d, const void* g) {
    asm volatile("cp.async.cg.shared.global [%0], [%1], 16;" :: "r"(d), "l"(g));
}
#define CP_COMMIT() asm volatile("cp.async.commit_group;" ::: "memory")
#define CP_WAIT(n)  asm volatile("cp.async.wait_group %0;" :: "n"(n) : "memory")

__device__ __forceinline__ void ldsm_x4(uint32_t* r, uint32_t addr) {
    asm volatile("ldmatrix.sync.aligned.m8n8.x4.shared.b16 {%0,%1,%2,%3}, [%4];"
                 : "=r"(r[0]), "=r"(r[1]), "=r"(r[2]), "=r"(r[3]) : "r"(addr));
}
__device__ __forceinline__ void mma4(float* c, const uint32_t* a, uint32_t b0, uint32_t b1) {
    asm volatile("mma.sync.aligned.m16n8k16.row.col.f32.bf16.bf16.f32 "
        "{%0,%1,%2,%3}, {%4,%5,%6,%7}, {%8,%9}, {%0,%1,%2,%3};"
        : "+f"(c[0]), "+f"(c[1]), "+f"(c[2]), "+f"(c[3])
        : "r"(a[0]), "r"(a[1]), "r"(a[2]), "r"(a[3]), "r"(b0), "r"(b1));
}

// Shared compute: one 64-col K-chunk, 3-pass bf16-split, 10 n-frags per warp.
__device__ __forceinline__ void compute_chunk(uint32_t aH, uint32_t aL,
                                              uint32_t bH, uint32_t bL,
                                              int aRowByte, int bRowByte0,
                                              float acc[10][4]) {
#pragma unroll
    for (int kk = 0; kk < 4; kk++) {
        const int kb2 = kk * 32;
        uint32_t ah[4], al[4];
        ldsm_x4(ah, aH + aRowByte + kb2);
        ldsm_x4(al, aL + aRowByte + kb2);
#pragma unroll
        for (int fp = 0; fp < 5; fp++) {
            const int boff = bRowByte0 + fp * (16 * SA * 2) + kb2;
            uint32_t bh[4], bl[4];
            ldsm_x4(bh, bH + boff);
            ldsm_x4(bl, bL + boff);
            mma4(acc[2 * fp],     ah, bh[0], bh[2]);
            mma4(acc[2 * fp],     ah, bl[0], bl[2]);
            mma4(acc[2 * fp],     al, bh[0], bh[2]);
            mma4(acc[2 * fp + 1], ah, bh[1], bh[3]);
            mma4(acc[2 * fp + 1], ah, bl[1], bl[3]);
            mma4(acc[2 * fp + 1], al, bh[1], bh[3]);
        }
    }
}

// ---------------------------------------------------------------------------
// k_prex: split x -> bf16 hi/lo, row-major and transposed. grid (144,4)x256
// ---------------------------------------------------------------------------
__global__ void k_prex(const float* __restrict__ x) {
    __shared__ unsigned sh[64][65];
    const int k0 = blockIdx.x * 64, b0 = blockIdx.y * 64;
    const int tid = threadIdx.x;
#pragma unroll
    for (int i = 0; i < 16; i++) {
        int idx = tid + i * 256;
        int r = idx >> 6, c = idx & 63;
        size_t g = (size_t)(b0 + r) * KTOT + k0 + c;
        float v = x[g];
        __nv_bfloat16 h = __float2bfloat16_rn(v);
        __nv_bfloat16 l = __float2bfloat16_rn(v - __bfloat162float(h));
        g_xh[g] = h; g_xl[g] = l;
        sh[r][c] = ((unsigned)__bfloat16_as_ushort(l) << 16) | (unsigned)__bfloat16_as_ushort(h);
    }
    __syncthreads();
#pragma unroll
    for (int i = 0; i < 16; i++) {
        int idx = tid + i * 256;
        int rr = idx >> 6, cc = idx & 63;
        unsigned p = sh[cc][rr];
        size_t g = (size_t)(k0 + rr) * B_ + b0 + cc;
        g_xth[g] = __ushort_as_bfloat16((unsigned short)(p & 0xFFFF));
        g_xtl[g] = __ushort_as_bfloat16((unsigned short)(p >> 16));
    }
}

// ---------------------------------------------------------------------------
// k_pre_w: W[j,n,u,i] -> Wnk[nu][k], Wkn[k][nu], iter-0 scaled split; logits=0.
// grid 144x256
// ---------------------------------------------------------------------------
__global__ void k_pre_w(const float* __restrict__ W) {
    __shared__ float sm[8 * 1281];
    const int j0 = blockIdx.x * 8;
    const int tid = threadIdx.x;
#pragma unroll
    for (int i = 0; i < 40; i++) {
        int idx = tid + i * 256;
        int jl = idx / 1280, rem = idx - jl * 1280;
        sm[jl * 1281 + rem] = W[(size_t)(j0 + jl) * 1280 + rem];
    }
    __syncthreads();
#pragma unroll
    for (int t = 0; t < 40; t++) {
        int idx = tid + t * 256;                 // = nu*64 + ii*8 + jl
        int jl = idx & 7, ii = (idx >> 3) & 7, nu = idx >> 6;
        float v = sm[jl * 1281 + nu * 8 + ii];
        size_t gi = (size_t)nu * KTOT + ii * IC + j0 + jl;
        g_Wnk[gi] = v;
        float vs = v * (1.0f / (float)IC);       // iter-0 c is uniform
        __nv_bfloat16 h = __float2bfloat16_rn(vs);
        g_SWth[gi] = h;
        g_SWtl[gi] = __float2bfloat16_rn(vs - __bfloat162float(h));
    }
#pragma unroll
    for (int t = 0; t < 40; t++) {
        int idx = tid + t * 256;                 // = (ii*8 + jl)*160 + nu
        int nu = idx % 160, rest = idx / 160;
        int jl = rest & 7, ii = rest >> 3;
        g_Wkn[(size_t)(ii * IC + j0 + jl) * NUU + nu] = sm[jl * 1281 + nu * 8 + ii];
    }
    int gidx = blockIdx.x * 256 + tid;
    if (gidx < IC * NU_) g_logits[gidx] = 0.0f;
}

// ---------------------------------------------------------------------------
// k_scale: SWt_{hi,lo}[nu][k] = split(Wnk[nu][k] * c[n][j]). grid 160x256
// ---------------------------------------------------------------------------
__global__ void k_scale() {
    __shared__ float cs[IC];
    const int nu = blockIdx.x;
    const int n = nu >> 4;
    const int tid = threadIdx.x;
    for (int t = tid; t < IC; t += 256) cs[t] = g_ct[n * IC + t];
    __syncthreads();
#pragma unroll
    for (int i = 0; i < 9; i++) {
        int e4 = tid + i * 256;
        int k = e4 * 4;
        int j = k % IC;
        float4 w = *reinterpret_cast<const float4*>(g_Wnk + (size_t)nu * KTOT + k);
        float v0 = w.x * cs[j], v1 = w.y * cs[j + 1], v2 = w.z * cs[j + 2], v3 = w.w * cs[j + 3];
        __nv_bfloat16 h0 = __float2bfloat16_rn(v0), h1 = __float2bfloat16_rn(v1);
        __nv_bfloat16 h2 = __float2bfloat16_rn(v2), h3 = __float2bfloat16_rn(v3);
        __nv_bfloat16 l0 = __float2bfloat16_rn(v0 - __bfloat162float(h0));
        __nv_bfloat16 l1 = __float2bfloat16_rn(v1 - __bfloat162float(h1));
        __nv_bfloat16 l2 = __float2bfloat16_rn(v2 - __bfloat162float(h2));
        __nv_bfloat16 l3 = __float2bfloat16_rn(v3 - __bfloat162float(h3));
        uint2 ph, pl;
        ph.x = ((unsigned)__bfloat16_as_ushort(h1) << 16) | __bfloat16_as_ushort(h0);
        ph.y = ((unsigned)__bfloat16_as_ushort(h3) << 16) | __bfloat16_as_ushort(h2);
        pl.x = ((unsigned)__bfloat16_as_ushort(l1) << 16) | __bfloat16_as_ushort(l0);
        pl.y = ((unsigned)__bfloat16_as_ushort(l3) << 16) | __bfloat16_as_ushort(l2);
        *reinterpret_cast<uint2*>(g_SWth + (size_t)nu * KTOT + k) = ph;
        *reinterpret_cast<uint2*>(g_SWtl + (size_t)nu * KTOT + k) = pl;
    }
}

// ---------------------------------------------------------------------------
// GEMM1: Spart[ks][b-tile 64][nu] = X * (c.W)^T over 256-k chunk. grid 144x256.
// (identical to R4 known-good)
// ---------------------------------------------------------------------------
#define BUF1 (448 * SA * 2)          // 64512 B
#define G1_SMEM (2 * BUF1)           // 129024

__device__ __forceinline__ void g1_load(uint32_t sb, int m0, int col, int tid) {
#pragma unroll
    for (int t = 0; t < 2; t++) {
        int idx = tid + t * 256;
        int r = idx >> 3, q = idx & 7;
        uint32_t d = sb + (uint32_t)(r * SA + q * 8) * 2;
        size_t g = (size_t)(m0 + r) * KTOT + col + q * 8;
        cpasync(d, g_xh + g);
        cpasync(d + 64 * SA * 2, g_xl + g);
    }
#pragma unroll
    for (int t = 0; t < 5; t++) {
        int idx = tid + t * 256;
        int r = idx >> 3, q = idx & 7;
        uint32_t d = sb + 128 * SA * 2 + (uint32_t)(r * SA + q * 8) * 2;
        size_t g = (size_t)r * KTOT + col + q * 8;
        cpasync(d, g_SWth + g);
        cpasync(d + 160 * SA * 2, g_SWtl + g);
    }
}

__global__ void __launch_bounds__(256) k_hmma1() {
    extern __shared__ char sm[];
    const int mt = blockIdx.x & 3, ks = blockIdx.x >> 2;
    const int m0 = mt * 64, kbase = ks * 256;
    const int tid = threadIdx.x, warp = tid >> 5, lane = tid & 31;
    const int wm = warp & 3, wn = warp >> 2;
    const int lg = lane >> 2, lt = lane & 3;
    const uint32_t sb = smem_to_u32(sm);

    const int aRowByte = ((wm * 16 + (lane & 15)) * SA + (lane >> 4) * 8) * 2;
    const int bRowByte0 = ((wn * 80 + (lane & 15)) * SA + (lane >> 4) * 8) * 2;

    float acc[10][4];
#pragma unroll
    for (int f = 0; f < 10; f++)
#pragma unroll
        for (int q = 0; q < 4; q++) acc[f][q] = 0.0f;

    g1_load(sb,        m0, kbase,      tid); CP_COMMIT();
    g1_load(sb + BUF1, m0, kbase + 64, tid); CP_COMMIT();

#define G1_BUFS(base) (base), (base) + 64 * SA * 2, (base) + 128 * SA * 2, (base) + 288 * SA * 2

    CP_WAIT(1); __syncthreads();
    compute_chunk(G1_BUFS(sb), aRowByte, bRowByte0, acc);
    __syncthreads();
    g1_load(sb, m0, kbase + 128, tid); CP_COMMIT();

    CP_WAIT(1); __syncthreads();
    compute_chunk(G1_BUFS(sb + BUF1), aRowByte, bRowByte0, acc);
    __syncthreads();
    g1_load(sb + BUF1, m0, kbase + 192, tid); CP_COMMIT();

    CP_WAIT(1); __syncthreads();
    compute_chunk(G1_BUFS(sb), aRowByte, bRowByte0, acc);

    CP_WAIT(0); __syncthreads();
    compute_chunk(G1_BUFS(sb + BUF1), aRowByte, bRowByte0, acc);

    float* base = g_Spart + (size_t)ks * (B_ * NUU);
    const int r0 = m0 + wm * 16 + lg;
#pragma unroll
    for (int f = 0; f < 10; f++) {
        const int nu = wn * 80 + f * 8 + lt * 2;
        *reinterpret_cast<float2*>(base + (size_t)r0 * NUU + nu)       = make_float2(acc[f][0], acc[f][1]);
        *reinterpret_cast<float2*>(base + (size_t)(r0 + 8) * NUU + nu) = make_float2(acc[f][2], acc[f][3]);
    }
}

// ---------------------------------------------------------------------------
// GEMM2 + fused b-update partials:
//   G[k,nu] = sum_{b in half} Xt[k][b] Vt[nu][b];
//   bp[i*2+bsplit][j][n] = sum_u Wkn[k][nu]*G[k][nu]   (k = i*IC + j)
// grid 144 (= kt 0..71 x bsplit), 512 threads. Mainloop identical to R4.
// ---------------------------------------------------------------------------
#define BUF2 (576 * SA * 2)          // 82944 B
#define G2_SMEM (2 * BUF2)           // 165888

__device__ __forceinline__ void g2_load(uint32_t sb, int k0, int col, int tid) {
#pragma unroll
    for (int t = 0; t < 2; t++) {
        int idx = tid + t * 512;
        int r = idx >> 3, q = idx & 7;
        uint32_t d = sb + (uint32_t)(r * SA + q * 8) * 2;
        size_t g = (size_t)(k0 + r) * B_ + col + q * 8;
        cpasync(d, g_xth + g);
        cpasync(d + 128 * SA * 2, g_xtl + g);
    }
#pragma unroll
    for (int t = 0; t < 3; t++) {
        int idx = tid + t * 512;
        if (idx < 1280) {
            int r = idx >> 3, q = idx & 7;
            uint32_t d = sb + 256 * SA * 2 + (uint32_t)(r * SA + q * 8) * 2;
            size_t g = (size_t)r * B_ + col + q * 8;
            cpasync(d, g_Vth + g);
            cpasync(d + 160 * SA * 2, g_Vtl + g);
        }
    }
}

__global__ void __launch_bounds__(512) k_hmma2() {
    extern __shared__ char sm[];
    const int ksp = blockIdx.x & 1;
    const int k0 = (blockIdx.x >> 1) * 128;
    const int col0 = ksp * 128;
    const int tid = threadIdx.x, warp = tid >> 5, lane = tid & 31;
    const int wm = warp >> 1, wn = warp & 1;
    const int lg = lane >> 2, lt = lane & 3;
    const uint32_t sb = smem_to_u32(sm);

    const int aRowByte = ((wm * 16 + (lane & 15)) * SA + (lane >> 4) * 8) * 2;
    const int bRowByte0 = ((wn * 80 + (lane & 15)) * SA + (lane >> 4) * 8) * 2;

    float acc[10][4];
#pragma unroll
    for (int f = 0; f < 10; f++)
#pragma unroll
        for (int q = 0; q < 4; q++) acc[f][q] = 0.0f;

    g2_load(sb,        k0, col0,      tid); CP_COMMIT();
    g2_load(sb + BUF2, k0, col0 + 64, tid); CP_COMMIT();

#define G2_BUFS(base) (base), (base) + 128 * SA * 2, (base) + 256 * SA * 2, (base) + 416 * SA * 2

    CP_WAIT(1); __syncthreads();
    compute_chunk(G2_BUFS(sb), aRowByte, bRowByte0, acc);

    CP_WAIT(0); __syncthreads();
    compute_chunk(G2_BUFS(sb + BUF2), aRowByte, bRowByte0, acc);

    // fused epilogue: contract with Wkn, quad-reduce over lt, emit bp partials.
    // 1152 = 9*128 so a 128-row k-tile never crosses an i boundary.
    const int i_idx = k0 / IC;
    const int j0 = k0 % IC;
    float* bp = g_bp + ((size_t)(i_idx * 2 + ksp) * IC + j0) * NU_;
    const int rbase = wm * 16 + lg;
#pragma unroll
    for (int rh = 0; rh < 2; rh++) {
        const int row = rbase + rh * 8;
        const float* wrow = g_Wkn + (size_t)(k0 + row) * NUU;
#pragma unroll
        for (int q = 0; q < 5; q++) {
            const int f0 = 2 * q;
            const int nu0 = wn * 80 + f0 * 8 + lt * 2;
            float2 w0 = *reinterpret_cast<const float2*>(wrow + nu0);
            float2 w1 = *reinterpret_cast<const float2*>(wrow + nu0 + 8);
            float s = acc[f0][rh * 2] * w0.x + acc[f0][rh * 2 + 1] * w0.y
                    + acc[f0 + 1][rh * 2] * w1.x + acc[f0 + 1][rh * 2 + 1] * w1.y;
            s += __shfl_xor_sync(0xffffffffu, s, 1);
            s += __shfl_xor_sync(0xffffffffu, s, 2);
            if (lt == 0) bp[(size_t)row * NU_ + wn * 5 + q] = s;
        }
    }
}

// ---------------------------------------------------------------------------
// k_squash: reduce split-K (3 groups of 12 in parallel), squash.
// grid 256, 480 threads.
// ---------------------------------------------------------------------------
__global__ void __launch_bounds__(480) k_squash(float* __restrict__ out, int final_iter) {
    const int b = blockIdx.x;
    const int tid = threadIdx.x;          // 0..479
    const int g = tid / NUU, t = tid - g * NUU;

    __shared__ float partial[3][NUU];
    __shared__ float sq[NUU];
    __shared__ float mag[US];

    float s = 0.0f;
#pragma unroll
    for (int q = 0; q < 12; q++)
        s += g_Spart[(size_t)(g * 12 + q) * (B_ * NUU) + b * NUU + t];
    partial[g][t] = s;
    __syncthreads();

    s = partial[0][t] + partial[1][t] + partial[2][t];   // valid for g==0 use below
    if (g == 0) sq[t] = s * s;
    __syncthreads();
    if (tid < US) {
        float m = 0.0f;
#pragma unroll
        for (int n = 0; n < NU_; n++) m += sq[n * US + tid];
        mag[tid] = m;
    }
    __syncthreads();
    if (g == 0) {
        float m = mag[t & 15];
        float v = s * (m / ((1.0f + m) * sqrtf(m)));
        if (final_iter) {
            out[b * NUU + t] = v;
        } else {
            __nv_bfloat16 h = __float2bfloat16_rn(v);
            __nv_bfloat16 l = __float2bfloat16_rn(v - __bfloat162float(h));
            g_Vth[t * B_ + b] = h;
            g_Vtl[t * B_ + b] = l;
        }
    }
}

// ---------------------------------------------------------------------------
// k_bred: logits[j,n] += (1/B) * sum_{p<16} bp[p][j][n]. grid 45x256
// ---------------------------------------------------------------------------
__global__ void k_bred() {
    int gid = blockIdx.x * 256 + threadIdx.x;
    if (gid >= IC * NU_) return;
    float s = 0.0f;
#pragma unroll
    for (int p = 0; p < 16; p++)
        s += g_bp[(size_t)p * (IC * NU_) + gid];
    g_logits[gid] += s * (1.0f / (float)B_);
}

// ---------------------------------------------------------------------------
// k_softmax over j for each n -> g_ct[n][j]. 1 block, 10 warps
// ---------------------------------------------------------------------------
__global__ void k_softmax() {
    const int t = threadIdx.x;
    const int n = t >> 5;
    const int lane = t & 31;
    float vals[36];
    float mx = -1e30f;
#pragma unroll
    for (int it = 0; it < 36; it++) {
        int j = lane + it * 32;
        vals[it] = g_logits[j * NU_ + n];
        mx = fmaxf(mx, vals[it]);
    }
#pragma unroll
    for (int off = 16; off; off >>= 1)
        mx = fmaxf(mx, __shfl_xor_sync(0xffffffffu, mx, off));
    float sum = 0.0f;
#pragma unroll
    for (int it = 0; it < 36; it++) { vals[it] = expf(vals[it] - mx); sum += vals[it]; }
#pragma unroll
    for (int off = 16; off; off >>= 1)
        sum += __shfl_xor_sync(0xffffffffu, sum, off);
    float inv = 1.0f / sum;
#pragma unroll
    for (int it = 0; it < 36; it++) {
        int j = lane + it * 32;
        g_ct[n * IC + j] = vals[it] * inv;
    }
}

// ---------------------------------------------------------------------------
extern "C" void kernel_launch(void* const* d_in, const int* in_sizes, int n_in,
                              void* d_out, int out_size) {
    const float* x = (const float*)d_in[0];   // [256, 8, 1152]
    const float* W = (const float*)d_in[1];   // [1152, 10, 16, 8]
    float* out = (float*)d_out;

    cudaFuncSetAttribute(k_hmma1, cudaFuncAttributeMaxDynamicSharedMemorySize, G1_SMEM);
    cudaFuncSetAttribute(k_hmma2, cudaFuncAttributeMaxDynamicSharedMemorySize, G2_SMEM);

    k_prex<<<dim3(KTOT / 64, B_ / 64), 256>>>(x);
    k_pre_w<<<IC / 8, 256>>>(W);              // also emits iter-0 scaled W split

    // iter 0 (no k_scale: c uniform, folded into k_pre_w)
    k_hmma1<<<4 * KSPLIT, 256, G1_SMEM>>>();
    k_squash<<<B_, 480>>>(nullptr, 0);
    k_hmma2<<<144, 512, G2_SMEM>>>();
    k_bred<<<45, 256>>>();
    k_softmax<<<1, 320>>>();
    // iter 1
    k_scale<<<NUU, 256>>>();
    k_hmma1<<<4 * KSPLIT, 256, G1_SMEM>>>();
    k_squash<<<B_, 480>>>(nullptr, 0);
    k_hmma2<<<144, 512, G2_SMEM>>>();
    k_bred<<<45, 256>>>();
    k_softmax<<<1, 320>>>();
    // iter 2 (final)
    k_scale<<<NUU, 256>>>();
    k_hmma1<<<4 * KSPLIT, 256, G1_SMEM>>>();
    k_squash<<<B_, 480>>>(out, 1);
}